// round 6
// baseline (speedup 1.0000x reference)
#include <cuda_runtime.h>
#include <math.h>
#include <stdint.h>

#define NSEQ 1024
#define DMOD 512
#define NHEAD 16
#define HDIM 32
#define DZ 128
#define NN (NSEQ*NSEQ)
#define QSCALE 0.17677669529663687f

__device__ float g_sln[NSEQ*DMOD];
__device__ float g_q[NHEAD*NSEQ*HDIM];
__device__ float g_k[NHEAD*NSEQ*HDIM];
__device__ float g_v[NHEAD*NSEQ*HDIM];
__device__ float g_gate[NSEQ*DMOD];
__device__ float g_o[NSEQ*DMOD];
__device__ float g_scores[NHEAD*NN];   // holds zb only (flash never materializes scores)
__device__ float g_wzp[DZ*NHEAD];
__device__ float g_alpha[NHEAD];
__device__ float g_beta[NHEAD];

// ---- packed f32x2 helpers (Blackwell FFMA2; PTX-only) ----
typedef unsigned long long u64;
__device__ __forceinline__ u64 pk(float x, float y) {
    u64 r; asm("mov.b64 %0, {%1,%2};" : "=l"(r) : "f"(x), "f"(y)); return r;
}
__device__ __forceinline__ void upk(u64 v, float& lo, float& hi) {
    asm("mov.b64 {%0,%1}, %2;" : "=f"(lo), "=f"(hi) : "l"(v));
}
__device__ __forceinline__ void ffma2(u64& d, u64 a, u64 b) {
    asm("fma.rn.f32x2 %0, %1, %2, %0;" : "+l"(d) : "l"(a), "l"(b));
}
__device__ __forceinline__ void fadd2(u64& d, u64 a) {
    asm("add.rn.f32x2 %0, %1, %0;" : "+l"(d) : "l"(a));
}

__global__ void prep_kernel(const float* __restrict__ Wz,
                            const float* __restrict__ zw,
                            const float* __restrict__ zb)
{
    int t = threadIdx.x;
    for (int i = t; i < DZ*NHEAD; i += blockDim.x)
        g_wzp[i] = zw[i >> 4] * Wz[i];
    if (t < NHEAD) {
        float a = 0.f, b = 0.f;
        for (int c = 0; c < DZ; c++) {
            float wv = Wz[c*NHEAD + t];
            a += zw[c] * wv;
            b += zb[c] * wv;
        }
        g_alpha[t] = a;
        g_beta[t]  = b;
    }
}

__global__ __launch_bounds__(128) void ln_s_kernel(const float* __restrict__ s,
                                                   const float* __restrict__ w,
                                                   const float* __restrict__ b)
{
    __shared__ float sred[8];
    __shared__ float s_mu, s_rstd;
    int row = blockIdx.x, tid = threadIdx.x;
    float4 v = *(const float4*)&s[row*DMOD + tid*4];
    float sum = v.x + v.y + v.z + v.w;
    float ssq = v.x*v.x + v.y*v.y + v.z*v.z + v.w*v.w;
    #pragma unroll
    for (int o = 16; o; o >>= 1) {
        sum += __shfl_xor_sync(0xffffffffu, sum, o);
        ssq += __shfl_xor_sync(0xffffffffu, ssq, o);
    }
    int lane = tid & 31, wid = tid >> 5;
    if (lane == 0) { sred[wid] = sum; sred[4 + wid] = ssq; }
    __syncthreads();
    if (tid == 0) {
        float a = sred[0]+sred[1]+sred[2]+sred[3];
        float q = sred[4]+sred[5]+sred[6]+sred[7];
        float mu = a * (1.f/DMOD);
        float var = q * (1.f/DMOD) - mu*mu;
        s_mu = mu; s_rstd = rsqrtf(var + 1e-5f);
    }
    __syncthreads();
    float mu = s_mu, rstd = s_rstd;
    float4 wv = *(const float4*)&w[tid*4];
    float4 bv = *(const float4*)&b[tid*4];
    float4 o;
    o.x = (v.x-mu)*rstd*wv.x + bv.x;
    o.y = (v.y-mu)*rstd*wv.y + bv.y;
    o.z = (v.z-mu)*rstd*wv.z + bv.z;
    o.w = (v.w-mu)*rstd*wv.w + bv.w;
    *(float4*)&g_sln[row*DMOD + tid*4] = o;
}

// Double-buffered 64x64x512 GEMM.
// mode_sel=-1: mode=blockIdx.z (0 q,1 k,2 v,3 gate). mode_sel=4: out=(g_o*g_gate)@Wo.
__global__ __launch_bounds__(256) void gemm_fused(
    const float* __restrict__ Wq, const float* __restrict__ Wk,
    const float* __restrict__ Wv, const float* __restrict__ Wg,
    const float* __restrict__ bq, const float* __restrict__ Wo,
    float* __restrict__ Cout, int mode_sel)
{
    __shared__ float As[2][16][68];
    __shared__ float Bs[2][16][64];
    int mode = (mode_sel < 0) ? (int)blockIdx.z : mode_sel;
    const float* Bm = (mode==0)?Wq:(mode==1)?Wk:(mode==2)?Wv:(mode==3)?Wg:Wo;
    const float* A  = (mode==4)? g_o : g_sln;
    int tid = threadIdx.x;
    int tx = tid & 15, ty = tid >> 4;
    int row0 = blockIdx.y*64, col0 = blockIdx.x*64;
    int arow = tid >> 2, ak = (tid & 3) << 2;
    int bk = tid >> 4, bc = (tid & 15) << 2;
    const float* Aptr = &A[(row0+arow)*DMOD + ak];
    const float* Gptr = &g_gate[(row0+arow)*DMOD + ak];
    const float* Bptr = &Bm[bk*DMOD + col0 + bc];

    float4 av = *(const float4*)Aptr;
    if (mode == 4) {
        float4 gv = *(const float4*)Gptr;
        av.x*=gv.x; av.y*=gv.y; av.z*=gv.z; av.w*=gv.w;
    }
    float4 bv = *(const float4*)Bptr;
    As[0][ak+0][arow]=av.x; As[0][ak+1][arow]=av.y;
    As[0][ak+2][arow]=av.z; As[0][ak+3][arow]=av.w;
    *(float4*)&Bs[0][bk][bc] = bv;
    __syncthreads();

    float acc[4][4] = {};
    int buf = 0;
    for (int k0 = 16; k0 < DMOD; k0 += 16) {
        float4 av2 = *(const float4*)(Aptr + k0);
        if (mode == 4) {
            float4 gv = *(const float4*)(Gptr + k0);
            av2.x*=gv.x; av2.y*=gv.y; av2.z*=gv.z; av2.w*=gv.w;
        }
        float4 bv2 = *(const float4*)(Bptr + (size_t)k0*DMOD);
        #pragma unroll
        for (int kk = 0; kk < 16; kk++) {
            float4 a4 = *(const float4*)&As[buf][kk][ty << 2];
            float4 b4 = *(const float4*)&Bs[buf][kk][tx << 2];
            float ar[4] = {a4.x,a4.y,a4.z,a4.w};
            float br[4] = {b4.x,b4.y,b4.z,b4.w};
            #pragma unroll
            for (int i = 0; i < 4; i++)
                #pragma unroll
                for (int j = 0; j < 4; j++)
                    acc[i][j] = fmaf(ar[i], br[j], acc[i][j]);
        }
        As[buf^1][ak+0][arow]=av2.x; As[buf^1][ak+1][arow]=av2.y;
        As[buf^1][ak+2][arow]=av2.z; As[buf^1][ak+3][arow]=av2.w;
        *(float4*)&Bs[buf^1][bk][bc] = bv2;
        __syncthreads();
        buf ^= 1;
    }
    #pragma unroll
    for (int kk = 0; kk < 16; kk++) {
        float4 a4 = *(const float4*)&As[buf][kk][ty << 2];
        float4 b4 = *(const float4*)&Bs[buf][kk][tx << 2];
        float ar[4] = {a4.x,a4.y,a4.z,a4.w};
        float br[4] = {b4.x,b4.y,b4.z,b4.w};
        #pragma unroll
        for (int i = 0; i < 4; i++)
            #pragma unroll
            for (int j = 0; j < 4; j++)
                acc[i][j] = fmaf(ar[i], br[j], acc[i][j]);
    }

    int row = row0 + (ty << 2), col = col0 + (tx << 2);
    if (mode <= 2) {
        float* dst = (mode == 0) ? g_q : (mode == 1 ? g_k : g_v);
        float bb[4] = {0.f,0.f,0.f,0.f};
        if (mode == 0) {
            float4 bia = *(const float4*)&bq[col];
            bb[0]=bia.x; bb[1]=bia.y; bb[2]=bia.z; bb[3]=bia.w;
        }
        #pragma unroll
        for (int i = 0; i < 4; i++)
            #pragma unroll
            for (int j = 0; j < 4; j++) {
                int cc = col + j;
                float v = acc[i][j];
                if (mode == 0) v = (v + bb[j]) * QSCALE;
                dst[((cc >> 5)*NSEQ + (row + i))*HDIM + (cc & 31)] = v;
            }
    } else if (mode == 3) {
        #pragma unroll
        for (int i = 0; i < 4; i++)
            #pragma unroll
            for (int j = 0; j < 4; j++)
                g_gate[(row+i)*DMOD + col+j] = 1.f/(1.f + __expf(-acc[i][j]));
    } else {
        #pragma unroll
        for (int i = 0; i < 4; i++)
            *(float4*)&Cout[(row+i)*DMOD + col] =
                make_float4(acc[i][0], acc[i][1], acc[i][2], acc[i][3]);
    }
}

// fused LN(z)@Wz -> g_scores[h][q][k]; single pass over z.
// Thread = one z-row, all 16 heads. wz loads are full-warp broadcasts.
// Register prefetch of next 128B chunk overlaps DRAM with compute.
__global__ __launch_bounds__(256) void zbias_kernel(const float* __restrict__ z)
{
    __shared__ float wz_s[DZ][NHEAD];    // 8 KB [c][h], 64B rows (16B aligned)
    __shared__ float ab_s[2*NHEAD];
    __shared__ float zs[8][32][36];      // per-warp 32x32 transpose tile (pad 4)
    int tid = threadIdx.x;
    int lane = tid & 31, w = tid >> 5;
    for (int i = tid; i < DZ*NHEAD; i += 256)
        wz_s[i >> 4][i & 15] = g_wzp[i];
    if (tid < 32) ab_s[tid] = (tid < 16) ? g_alpha[tid] : g_beta[tid - 16];
    __syncthreads();

    int row0w = blockIdx.x*256 + w*32;
    const float* zwarp = z + (size_t)row0w * DZ;

    u64 acc2[8];             // 16 heads, packed pairs
    u64 sum2 = 0ull, ssq2 = 0ull;
    #pragma unroll
    for (int i = 0; i < 8; i++) acc2[i] = 0ull;

    int lr8 = lane >> 3, lc8 = (lane & 7) << 2;
    float4 pf[8];
    #pragma unroll
    for (int j = 0; j < 8; j++)
        pf[j] = *(const float4*)&zwarp[(size_t)(j*4 + lr8)*DZ + lc8];

    for (int ch = 0; ch < 4; ch++) {
        #pragma unroll
        for (int j = 0; j < 8; j++)
            *(float4*)&zs[w][j*4 + lr8][lc8] = pf[j];
        __syncwarp();
        if (ch < 3) {
            #pragma unroll
            for (int j = 0; j < 8; j++)
                pf[j] = *(const float4*)&zwarp[(size_t)(j*4 + lr8)*DZ + (ch+1)*32 + lc8];
        }
        #pragma unroll
        for (int c4 = 0; c4 < 8; c4++) {
            float4 v = *(const float4*)&zs[w][lane][c4 << 2];
            u64 v01 = pk(v.x, v.y), v23 = pk(v.z, v.w);
            fadd2(sum2, v01); fadd2(sum2, v23);
            ffma2(ssq2, v01, v01); ffma2(ssq2, v23, v23);
            int cg = ch*32 + (c4 << 2);
            float vr[4] = {v.x, v.y, v.z, v.w};
            #pragma unroll
            for (int cc = 0; cc < 4; cc++) {
                u64 vv = pk(vr[cc], vr[cc]);
                const float* wr = &wz_s[cg + cc][0];
                ulonglong2 wa = *(const ulonglong2*)&wr[0];
                ulonglong2 wb = *(const ulonglong2*)&wr[4];
                ulonglong2 wc = *(const ulonglong2*)&wr[8];
                ulonglong2 wd = *(const ulonglong2*)&wr[12];
                ffma2(acc2[0], vv, wa.x); ffma2(acc2[1], vv, wa.y);
                ffma2(acc2[2], vv, wb.x); ffma2(acc2[3], vv, wb.y);
                ffma2(acc2[4], vv, wc.x); ffma2(acc2[5], vv, wc.y);
                ffma2(acc2[6], vv, wd.x); ffma2(acc2[7], vv, wd.y);
            }
        }
        __syncwarp();
    }

    float slo, shi, qlo, qhi;
    upk(sum2, slo, shi); upk(ssq2, qlo, qhi);
    float sum = slo + shi, ssq = qlo + qhi;
    float mu = sum * (1.f/DZ);
    float var = ssq * (1.f/DZ) - mu*mu;
    float rstd = rsqrtf(var + 1e-5f);
    int row = row0w + lane;
    #pragma unroll
    for (int p = 0; p < 8; p++) {
        float a0, a1;
        upk(acc2[p], a0, a1);
        int h = p << 1;
        g_scores[(size_t)(h+0)*NN + row] = rstd*(a0 - mu*ab_s[h+0]) + ab_s[16+h+0];
        g_scores[(size_t)(h+1)*NN + row] = rstd*(a1 - mu*ab_s[h+1]) + ab_s[16+h+1];
    }
}

// Flash attention: one block per (q-tile 64, head). S=QK^T+zb, online softmax, O=P@V.
__global__ __launch_bounds__(256) void flash_kernel()
{
    __shared__ float Qs[32][68];
    __shared__ float Ks[32][68];
    __shared__ float Vs[64][36];
    __shared__ float Ps[64][68];
    __shared__ float corr_s[64];
    __shared__ float l_s[64];
    int tid = threadIdx.x;
    int h = blockIdx.y, q0 = blockIdx.x*64;
    const float* qb = g_q + h*NSEQ*HDIM;
    const float* kp = g_k + h*NSEQ*HDIM;
    const float* vp = g_v + h*NSEQ*HDIM;
    const float* zp = g_scores + (size_t)h*NN;

    int lr = tid >> 2;
    int lc = (tid & 3) << 2;
    {
        float4 a = *(const float4*)&qb[(q0+lr)*HDIM + lc];
        float4 b = *(const float4*)&qb[(q0+lr)*HDIM + lc + 16];
        Qs[lc+0][lr]=a.x; Qs[lc+1][lr]=a.y; Qs[lc+2][lr]=a.z; Qs[lc+3][lr]=a.w;
        Qs[lc+16][lr]=b.x; Qs[lc+17][lr]=b.y; Qs[lc+18][lr]=b.z; Qs[lc+19][lr]=b.w;
    }
    int tx = tid & 15, ty = tid >> 4;
    int oty = tid >> 3, otx = tid & 7;
    int vc = (tid & 3) << 3;
    float m[4], l[4];
    #pragma unroll
    for (int i = 0; i < 4; i++) { m[i] = -1e30f; l[i] = 0.f; }
    float oacc[2][4] = {};

    for (int kb0 = 0; kb0 < NSEQ; kb0 += 64) {
        float4 ka = *(const float4*)&kp[(kb0+lr)*HDIM + lc];
        float4 kc2 = *(const float4*)&kp[(kb0+lr)*HDIM + lc + 16];
        float4 v0 = *(const float4*)&vp[(kb0+lr)*HDIM + vc];
        float4 v1 = *(const float4*)&vp[(kb0+lr)*HDIM + vc + 4];
        __syncthreads();
        Ks[lc+0][lr]=ka.x; Ks[lc+1][lr]=ka.y; Ks[lc+2][lr]=ka.z; Ks[lc+3][lr]=ka.w;
        Ks[lc+16][lr]=kc2.x; Ks[lc+17][lr]=kc2.y; Ks[lc+18][lr]=kc2.z; Ks[lc+19][lr]=kc2.w;
        *(float4*)&Vs[lr][vc] = v0;
        *(float4*)&Vs[lr][vc+4] = v1;
        __syncthreads();

        float s[4][4];
        #pragma unroll
        for (int i = 0; i < 4; i++) {
            float4 z4 = *(const float4*)&zp[(size_t)(q0+(ty<<2)+i)*NSEQ + kb0 + (tx<<2)];
            s[i][0]=z4.x; s[i][1]=z4.y; s[i][2]=z4.z; s[i][3]=z4.w;
        }
        #pragma unroll
        for (int kk = 0; kk < 32; kk++) {
            float4 a4 = *(const float4*)&Qs[kk][ty << 2];
            float4 b4 = *(const float4*)&Ks[kk][tx << 2];
            float ar[4] = {a4.x,a4.y,a4.z,a4.w};
            float br[4] = {b4.x,b4.y,b4.z,b4.w};
            #pragma unroll
            for (int i = 0; i < 4; i++)
                #pragma unroll
                for (int j = 0; j < 4; j++)
                    s[i][j] = fmaf(ar[i], br[j], s[i][j]);
        }
        #pragma unroll
        for (int i = 0; i < 4; i++) {
            float mx = fmaxf(fmaxf(s[i][0],s[i][1]), fmaxf(s[i][2],s[i][3]));
            mx = fmaxf(mx, __shfl_xor_sync(0xffffffffu, mx, 1));
            mx = fmaxf(mx, __shfl_xor_sync(0xffffffffu, mx, 2));
            mx = fmaxf(mx, __shfl_xor_sync(0xffffffffu, mx, 4));
            mx = fmaxf(mx, __shfl_xor_sync(0xffffffffu, mx, 8));
            float mnew = fmaxf(m[i], mx);
            float c = __expf(m[i] - mnew);
            s[i][0] = __expf(s[i][0]-mnew); s[i][1] = __expf(s[i][1]-mnew);
            s[i][2] = __expf(s[i][2]-mnew); s[i][3] = __expf(s[i][3]-mnew);
            float rs = s[i][0]+s[i][1]+s[i][2]+s[i][3];
            rs += __shfl_xor_sync(0xffffffffu, rs, 1);
            rs += __shfl_xor_sync(0xffffffffu, rs, 2);
            rs += __shfl_xor_sync(0xffffffffu, rs, 4);
            rs += __shfl_xor_sync(0xffffffffu, rs, 8);
            l[i] = l[i]*c + rs;
            m[i] = mnew;
            int row = (ty << 2) + i;
            if (tx == 0) { corr_s[row] = c; l_s[row] = l[i]; }
            *(float4*)&Ps[row][tx << 2] = make_float4(s[i][0],s[i][1],s[i][2],s[i][3]);
        }
        __syncthreads();

        float c0 = corr_s[oty*2], c1 = corr_s[oty*2+1];
        #pragma unroll
        for (int j = 0; j < 4; j++) { oacc[0][j] *= c0; oacc[1][j] *= c1; }
        #pragma unroll
        for (int kk = 0; kk < 64; kk++) {
            float p0 = Ps[oty*2][kk];
            float p1 = Ps[oty*2+1][kk];
            float4 vv = *(const float4*)&Vs[kk][otx << 2];
            oacc[0][0]=fmaf(p0,vv.x,oacc[0][0]); oacc[0][1]=fmaf(p0,vv.y,oacc[0][1]);
            oacc[0][2]=fmaf(p0,vv.z,oacc[0][2]); oacc[0][3]=fmaf(p0,vv.w,oacc[0][3]);
            oacc[1][0]=fmaf(p1,vv.x,oacc[1][0]); oacc[1][1]=fmaf(p1,vv.y,oacc[1][1]);
            oacc[1][2]=fmaf(p1,vv.z,oacc[1][2]); oacc[1][3]=fmaf(p1,vv.w,oacc[1][3]);
        }
    }
    float inv0 = 1.f / l_s[oty*2];
    float inv1 = 1.f / l_s[oty*2+1];
    *(float4*)&g_o[(q0 + oty*2 + 0)*DMOD + h*HDIM + (otx << 2)] =
        make_float4(oacc[0][0]*inv0, oacc[0][1]*inv0, oacc[0][2]*inv0, oacc[0][3]*inv0);
    *(float4*)&g_o[(q0 + oty*2 + 1)*DMOD + h*HDIM + (otx << 2)] =
        make_float4(oacc[1][0]*inv1, oacc[1][1]*inv1, oacc[1][2]*inv1, oacc[1][3]*inv1);
}

extern "C" void kernel_launch(void* const* d_in, const int* in_sizes, int n_in,
                              void* d_out, int out_size)
{
    const float* s   = (const float*)d_in[0];
    const float* z   = (const float*)d_in[1];
    const float* nsw = (const float*)d_in[2];
    const float* nsb = (const float*)d_in[3];
    const float* Wq  = (const float*)d_in[4];
    const float* bq  = (const float*)d_in[5];
    const float* Wk  = (const float*)d_in[6];
    const float* Wv  = (const float*)d_in[7];
    const float* Wg  = (const float*)d_in[8];
    const float* zw  = (const float*)d_in[9];
    const float* zb  = (const float*)d_in[10];
    const float* Wz  = (const float*)d_in[11];
    const float* Wo  = (const float*)d_in[12];
    float* out = (float*)d_out;

    prep_kernel<<<1, 256>>>(Wz, zw, zb);
    ln_s_kernel<<<NSEQ, 128>>>(s, nsw, nsb);
    gemm_fused<<<dim3(DMOD/64, NSEQ/64, 4), 256>>>(Wq, Wk, Wv, Wg, bq, Wo, nullptr, -1);
    zbias_kernel<<<NN/256, 256>>>(z);
    flash_kernel<<<dim3(NSEQ/64, NHEAD), 256>>>();
    gemm_fused<<<dim3(DMOD/64, NSEQ/64, 1), 256>>>(Wq, Wk, Wv, Wg, bq, Wo, out, 4);
}

// round 8
// speedup vs baseline: 1.2389x; 1.2389x over previous
#include <cuda_runtime.h>
#include <cuda_bf16.h>
#include <mma.h>
#include <math.h>
#include <stdint.h>

using namespace nvcuda;

#define NSEQ 1024
#define DMOD 512
#define NHEAD 16
#define HDIM 32
#define DZ 128
#define NN (NSEQ*NSEQ)
#define QSCALE 0.17677669529663687f

typedef unsigned long long u64;
typedef __nv_bfloat16 bf16;

__device__ float g_q[NHEAD*NSEQ*HDIM];
__device__ float g_k[NHEAD*NSEQ*HDIM];
__device__ float g_v[NHEAD*NSEQ*HDIM];
__device__ float g_gate[NSEQ*DMOD];
__device__ float g_o[NSEQ*DMOD];
__device__ float g_scores[NHEAD*NN];
__device__ float g_wzp[DZ*NHEAD];
__device__ float g_alpha[NHEAD];
__device__ float g_beta[NHEAD];
__device__ bf16 g_sa_hi[NSEQ*DMOD], g_sa_lo[NSEQ*DMOD];
__device__ bf16 g_oa_hi[NSEQ*DMOD], g_oa_lo[NSEQ*DMOD];
__device__ bf16 g_wt_hi[5*DMOD*DMOD], g_wt_lo[5*DMOD*DMOD];

// ---- packed f32x2 helpers (Blackwell FFMA2; PTX-only) ----
__device__ __forceinline__ u64 pk(float x, float y) {
    u64 r; asm("mov.b64 %0, {%1,%2};" : "=l"(r) : "f"(x), "f"(y)); return r;
}
__device__ __forceinline__ void upk(u64 v, float& lo, float& hi) {
    asm("mov.b64 {%0,%1}, %2;" : "=f"(lo), "=f"(hi) : "l"(v));
}
__device__ __forceinline__ void ffma2(u64& d, u64 a, u64 b) {
    asm("fma.rn.f32x2 %0, %1, %2, %0;" : "+l"(d) : "l"(a), "l"(b));
}
__device__ __forceinline__ void fadd2(u64& d, u64 a) {
    asm("add.rn.f32x2 %0, %1, %0;" : "+l"(d) : "l"(a));
}

__global__ void prep_kernel(const float* __restrict__ Wz,
                            const float* __restrict__ zw,
                            const float* __restrict__ zb)
{
    int t = threadIdx.x;
    for (int i = t; i < DZ*NHEAD; i += blockDim.x)
        g_wzp[i] = zw[i >> 4] * Wz[i];
    if (t < NHEAD) {
        float a = 0.f, b = 0.f;
        for (int c = 0; c < DZ; c++) {
            float wv = Wz[c*NHEAD + t];
            a += zw[c] * wv;
            b += zb[c] * wv;
        }
        g_alpha[t] = a;
        g_beta[t]  = b;
    }
}

__global__ __launch_bounds__(128) void ln_s_kernel(const float* __restrict__ s,
                                                   const float* __restrict__ w,
                                                   const float* __restrict__ b)
{
    __shared__ float sred[8];
    __shared__ float s_mu, s_rstd;
    int row = blockIdx.x, tid = threadIdx.x;
    float4 v = *(const float4*)&s[row*DMOD + tid*4];
    float sum = v.x + v.y + v.z + v.w;
    float ssq = v.x*v.x + v.y*v.y + v.z*v.z + v.w*v.w;
    #pragma unroll
    for (int o = 16; o; o >>= 1) {
        sum += __shfl_xor_sync(0xffffffffu, sum, o);
        ssq += __shfl_xor_sync(0xffffffffu, ssq, o);
    }
    int lane = tid & 31, wid = tid >> 5;
    if (lane == 0) { sred[wid] = sum; sred[4 + wid] = ssq; }
    __syncthreads();
    if (tid == 0) {
        float a = sred[0]+sred[1]+sred[2]+sred[3];
        float q = sred[4]+sred[5]+sred[6]+sred[7];
        float mu = a * (1.f/DMOD);
        float var = q * (1.f/DMOD) - mu*mu;
        s_mu = mu; s_rstd = rsqrtf(var + 1e-5f);
    }
    __syncthreads();
    float mu = s_mu, rstd = s_rstd;
    float4 wv = *(const float4*)&w[tid*4];
    float4 bv = *(const float4*)&b[tid*4];
    float o4[4];
    o4[0] = (v.x-mu)*rstd*wv.x + bv.x;
    o4[1] = (v.y-mu)*rstd*wv.y + bv.y;
    o4[2] = (v.z-mu)*rstd*wv.z + bv.z;
    o4[3] = (v.w-mu)*rstd*wv.w + bv.w;
    union { bf16 h[4]; uint2 u; } H, L;
    #pragma unroll
    for (int j = 0; j < 4; j++) {
        H.h[j] = __float2bfloat16(o4[j]);
        L.h[j] = __float2bfloat16(o4[j] - __bfloat162float(H.h[j]));
    }
    int idx = row*DMOD + tid*4;
    *(uint2*)&g_sa_hi[idx] = H.u;
    *(uint2*)&g_sa_lo[idx] = L.u;
}

// transpose + bf16-split weights: g_wt[g][n][k] = W_g[k][n]
__global__ void wtrans_kernel(const float* __restrict__ Wq, const float* __restrict__ Wk,
                              const float* __restrict__ Wv, const float* __restrict__ Wg,
                              const float* __restrict__ Wo)
{
    __shared__ float t[32][33];
    int g = blockIdx.z;
    const float* W = (g==0)?Wq:(g==1)?Wk:(g==2)?Wv:(g==3)?Wg:Wo;
    int tx = threadIdx.x, ty = threadIdx.y;
    int bx = blockIdx.x*32, by = blockIdx.y*32;
    #pragma unroll
    for (int i = 0; i < 4; i++)
        t[ty + 8*i][tx] = W[(size_t)(by + ty + 8*i)*DMOD + bx + tx];
    __syncthreads();
    size_t base = (size_t)g*DMOD*DMOD;
    #pragma unroll
    for (int i = 0; i < 4; i++) {
        int n = bx + ty + 8*i, k = by + tx;
        float v = t[tx][ty + 8*i];
        bf16 h = __float2bfloat16(v);
        g_wt_hi[base + (size_t)n*DMOD + k] = h;
        g_wt_lo[base + (size_t)n*DMOD + k] = __float2bfloat16(v - __bfloat162float(h));
    }
}

__global__ __launch_bounds__(256) void conv_o_kernel()
{
    int idx = (blockIdx.x*256 + threadIdx.x)*4;
    float4 o = *(const float4*)&g_o[idx];
    float4 g = *(const float4*)&g_gate[idx];
    float v[4] = {o.x*g.x, o.y*g.y, o.z*g.z, o.w*g.w};
    union { bf16 h[4]; uint2 u; } H, L;
    #pragma unroll
    for (int j = 0; j < 4; j++) {
        H.h[j] = __float2bfloat16(v[j]);
        L.h[j] = __float2bfloat16(v[j] - __bfloat162float(H.h[j]));
    }
    *(uint2*)&g_oa_hi[idx] = H.u;
    *(uint2*)&g_oa_lo[idx] = L.u;
}

// WMMA bf16-split GEMM (HMMA tensor pipe; compiles for plain sm_103 target).
// CTA tile 64x64, 8 warps of 16x32, K chunks of 64.
// mode -1: blockIdx.z in {0 q,1 k,2 v,3 gate}; mode 4: out = (o*gate)@Wo.
__global__ __launch_bounds__(256) void tc_gemm(const float* __restrict__ bq,
                                               float* __restrict__ Cout, int mode_sel)
{
    __shared__ __align__(16) char smbuf[4*64*72*2];   // 36864 B
    bf16* Ah_s = (bf16*)smbuf;
    bf16* Al_s = Ah_s + 64*72;
    bf16* Bh_s = Al_s + 64*72;
    bf16* Bl_s = Bh_s + 64*72;
    float* Cs  = (float*)smbuf;     // aliased after MMAs finish

    int mode = (mode_sel < 0) ? (int)blockIdx.z : mode_sel;
    const bf16* Ah = (mode==4) ? g_oa_hi : g_sa_hi;
    const bf16* Al = (mode==4) ? g_oa_lo : g_sa_lo;
    size_t wb = (size_t)((mode==4)?4:mode)*DMOD*DMOD;
    const bf16* Bh = g_wt_hi + wb;
    const bf16* Bl = g_wt_lo + wb;

    int tid = threadIdx.x;
    int w = tid >> 5, wr = w >> 1, wc = w & 1;
    int m0 = blockIdx.y*64, n0 = blockIdx.x*64;
    int lrow = tid >> 2, lseg = (tid & 3) << 4;   // 64 rows x 4 segs of 16 bf16

    wmma::fragment<wmma::accumulator,16,16,16,float> acc[2];
    wmma::fill_fragment(acc[0], 0.f);
    wmma::fill_fragment(acc[1], 0.f);

    const bf16* gAh = Ah + (size_t)(m0+lrow)*DMOD + lseg;
    const bf16* gAl = Al + (size_t)(m0+lrow)*DMOD + lseg;
    const bf16* gBh = Bh + (size_t)(n0+lrow)*DMOD + lseg;
    const bf16* gBl = Bl + (size_t)(n0+lrow)*DMOD + lseg;
    int soff = lrow*72 + lseg;

    for (int ch = 0; ch < 8; ch++) {
        uint4 a0 = *(const uint4*)(gAh + ch*64);
        uint4 a1 = *(const uint4*)(gAh + ch*64 + 8);
        uint4 a2 = *(const uint4*)(gAl + ch*64);
        uint4 a3 = *(const uint4*)(gAl + ch*64 + 8);
        uint4 b0 = *(const uint4*)(gBh + ch*64);
        uint4 b1 = *(const uint4*)(gBh + ch*64 + 8);
        uint4 b2 = *(const uint4*)(gBl + ch*64);
        uint4 b3 = *(const uint4*)(gBl + ch*64 + 8);
        if (ch) __syncthreads();                 // prev chunk's MMAs done
        *(uint4*)(Ah_s + soff)     = a0;
        *(uint4*)(Ah_s + soff + 8) = a1;
        *(uint4*)(Al_s + soff)     = a2;
        *(uint4*)(Al_s + soff + 8) = a3;
        *(uint4*)(Bh_s + soff)     = b0;
        *(uint4*)(Bh_s + soff + 8) = b1;
        *(uint4*)(Bl_s + soff)     = b2;
        *(uint4*)(Bl_s + soff + 8) = b3;
        __syncthreads();
        #pragma unroll
        for (int ks = 0; ks < 4; ks++) {
            wmma::fragment<wmma::matrix_a,16,16,16,bf16,wmma::row_major> fah, fal;
            wmma::load_matrix_sync(fah, Ah_s + (wr*16)*72 + ks*16, 72);
            wmma::load_matrix_sync(fal, Al_s + (wr*16)*72 + ks*16, 72);
            #pragma unroll
            for (int c = 0; c < 2; c++) {
                wmma::fragment<wmma::matrix_b,16,16,16,bf16,wmma::col_major> fbh, fbl;
                const bf16* bp = Bh_s + (wc*32 + c*16)*72 + ks*16;
                wmma::load_matrix_sync(fbh, bp, 72);
                wmma::load_matrix_sync(fbl, Bl_s + (wc*32 + c*16)*72 + ks*16, 72);
                wmma::mma_sync(acc[c], fah, fbh, acc[c]);
                wmma::mma_sync(acc[c], fah, fbl, acc[c]);
                wmma::mma_sync(acc[c], fal, fbh, acc[c]);
            }
        }
    }
    __syncthreads();
    wmma::store_matrix_sync(Cs + (wr*16)*72 + wc*32,      acc[0], 72, wmma::mem_row_major);
    wmma::store_matrix_sync(Cs + (wr*16)*72 + wc*32 + 16, acc[1], 72, wmma::mem_row_major);
    __syncthreads();

    // scatter epilogue: thread handles row lrow, 16 cols at n0+lseg
    int r = lrow;
    int colg = n0 + lseg;
    if (mode <= 2) {
        float* dst = (mode==0) ? g_q : (mode==1 ? g_k : g_v);
        float* dp = &dst[((size_t)(colg >> 5)*NSEQ + m0 + r)*HDIM + (colg & 31)];
        #pragma unroll
        for (int j = 0; j < 4; j++) {
            float4 v = *(float4*)&Cs[r*72 + lseg + j*4];
            if (mode == 0) {
                float4 bb = *(const float4*)&bq[colg + j*4];
                v.x = (v.x + bb.x)*QSCALE; v.y = (v.y + bb.y)*QSCALE;
                v.z = (v.z + bb.z)*QSCALE; v.w = (v.w + bb.w)*QSCALE;
            }
            *(float4*)&dp[j*4] = v;
        }
    } else if (mode == 3) {
        float* dp = &g_gate[(size_t)(m0 + r)*DMOD + colg];
        #pragma unroll
        for (int j = 0; j < 4; j++) {
            float4 v = *(float4*)&Cs[r*72 + lseg + j*4];
            v.x = 1.f/(1.f + __expf(-v.x)); v.y = 1.f/(1.f + __expf(-v.y));
            v.z = 1.f/(1.f + __expf(-v.z)); v.w = 1.f/(1.f + __expf(-v.w));
            *(float4*)&dp[j*4] = v;
        }
    } else {
        float* dp = &Cout[(size_t)(m0 + r)*DMOD + colg];
        #pragma unroll
        for (int j = 0; j < 4; j++)
            *(float4*)&dp[j*4] = *(float4*)&Cs[r*72 + lseg + j*4];
    }
}

// fused LN(z)@Wz -> g_scores[h][q][k]; single pass over z (R5 version, measured 149.5us)
__global__ __launch_bounds__(256) void zbias_kernel(const float* __restrict__ z)
{
    __shared__ float wz_s[DZ][NHEAD];
    __shared__ float ab_s[2*NHEAD];
    __shared__ float zs[8][32][36];
    int tid = threadIdx.x;
    int lane = tid & 31, w = tid >> 5;
    int tx = lane & 3, ty = lane >> 2;
    for (int i = tid; i < DZ*NHEAD; i += 256)
        wz_s[i >> 4][i & 15] = g_wzp[i];
    if (tid < 32) ab_s[tid] = (tid < 16) ? g_alpha[tid] : g_beta[tid - 16];
    __syncthreads();

    int row0w = blockIdx.x*256 + w*32;
    const float* zwarp = z + (size_t)row0w * DZ;

    u64 acc2[4][2];
    u64 sum2[4], ssq2[4];
    #pragma unroll
    for (int i = 0; i < 4; i++) {
        acc2[i][0] = 0ull; acc2[i][1] = 0ull;
        sum2[i] = 0ull; ssq2[i] = 0ull;
    }
    int lr8 = lane >> 3, lc8 = (lane & 7) << 2;

    for (int ch = 0; ch < 4; ch++) {
        #pragma unroll
        for (int j = 0; j < 8; j++) {
            float4 t = *(const float4*)&zwarp[(size_t)(j*4 + lr8)*DZ + ch*32 + lc8];
            *(float4*)&zs[w][j*4 + lr8][lc8] = t;
        }
        __syncwarp();
        #pragma unroll
        for (int c4 = 0; c4 < 8; c4++) {
            int cg = ch*32 + c4*4;
            u64 wp[4][2];
            #pragma unroll
            for (int cc = 0; cc < 4; cc++) {
                float4 wq = *(const float4*)&wz_s[cg + cc][tx << 2];
                wp[cc][0] = pk(wq.x, wq.y);
                wp[cc][1] = pk(wq.z, wq.w);
            }
            #pragma unroll
            for (int i = 0; i < 4; i++) {
                float4 v = *(const float4*)&zs[w][ty + 8*i][c4 << 2];
                u64 v01 = pk(v.x, v.y), v23 = pk(v.z, v.w);
                fadd2(sum2[i], v01); fadd2(sum2[i], v23);
                ffma2(ssq2[i], v01, v01); ffma2(ssq2[i], v23, v23);
                u64 vv;
                vv = pk(v.x, v.x); ffma2(acc2[i][0], vv, wp[0][0]); ffma2(acc2[i][1], vv, wp[0][1]);
                vv = pk(v.y, v.y); ffma2(acc2[i][0], vv, wp[1][0]); ffma2(acc2[i][1], vv, wp[1][1]);
                vv = pk(v.z, v.z); ffma2(acc2[i][0], vv, wp[2][0]); ffma2(acc2[i][1], vv, wp[2][1]);
                vv = pk(v.w, v.w); ffma2(acc2[i][0], vv, wp[3][0]); ffma2(acc2[i][1], vv, wp[3][1]);
            }
        }
        __syncwarp();
    }

    #pragma unroll
    for (int i = 0; i < 4; i++) {
        float slo, shi, qlo, qhi;
        upk(sum2[i], slo, shi); upk(ssq2[i], qlo, qhi);
        float sum = slo + shi, ssq = qlo + qhi;
        float mu = sum * (1.f/DZ);
        float var = ssq * (1.f/DZ) - mu*mu;
        float rstd = rsqrtf(var + 1e-5f);
        int row = row0w + ty + 8*i;
        float a0, a1, a2, a3;
        upk(acc2[i][0], a0, a1); upk(acc2[i][1], a2, a3);
        int h0 = tx << 2;
        g_scores[(size_t)(h0+0)*NN + row] = rstd*(a0 - mu*ab_s[h0+0]) + ab_s[16+h0+0];
        g_scores[(size_t)(h0+1)*NN + row] = rstd*(a1 - mu*ab_s[h0+1]) + ab_s[16+h0+1];
        g_scores[(size_t)(h0+2)*NN + row] = rstd*(a2 - mu*ab_s[h0+2]) + ab_s[16+h0+2];
        g_scores[(size_t)(h0+3)*NN + row] = rstd*(a3 - mu*ab_s[h0+3]) + ab_s[16+h0+3];
    }
}

// Flash attention: one block per (q-tile 64, head). S=QK^T+zb, online softmax, O=P@V.
__global__ __launch_bounds__(256) void flash_kernel()
{
    __shared__ float Qs[32][68];
    __shared__ float Ks[32][68];
    __shared__ float Vs[64][36];
    __shared__ float Ps[64][68];
    __shared__ float corr_s[64];
    __shared__ float l_s[64];
    int tid = threadIdx.x;
    int h = blockIdx.y, q0 = blockIdx.x*64;
    const float* qb = g_q + h*NSEQ*HDIM;
    const float* kp = g_k + h*NSEQ*HDIM;
    const float* vp = g_v + h*NSEQ*HDIM;
    const float* zp = g_scores + (size_t)h*NN;

    int lr = tid >> 2;
    int lc = (tid & 3) << 2;
    {
        float4 a = *(const float4*)&qb[(q0+lr)*HDIM + lc];
        float4 b = *(const float4*)&qb[(q0+lr)*HDIM + lc + 16];
        Qs[lc+0][lr]=a.x; Qs[lc+1][lr]=a.y; Qs[lc+2][lr]=a.z; Qs[lc+3][lr]=a.w;
        Qs[lc+16][lr]=b.x; Qs[lc+17][lr]=b.y; Qs[lc+18][lr]=b.z; Qs[lc+19][lr]=b.w;
    }
    int tx = tid & 15, ty = tid >> 4;
    int oty = tid >> 3, otx = tid & 7;
    int vc = (tid & 3) << 3;
    float m[4], l[4];
    #pragma unroll
    for (int i = 0; i < 4; i++) { m[i] = -1e30f; l[i] = 0.f; }
    float oacc[2][4] = {};

    for (int kb0 = 0; kb0 < NSEQ; kb0 += 64) {
        float4 ka = *(const float4*)&kp[(kb0+lr)*HDIM + lc];
        float4 kc2 = *(const float4*)&kp[(kb0+lr)*HDIM + lc + 16];
        float4 v0 = *(const float4*)&vp[(kb0+lr)*HDIM + vc];
        float4 v1 = *(const float4*)&vp[(kb0+lr)*HDIM + vc + 4];
        __syncthreads();
        Ks[lc+0][lr]=ka.x; Ks[lc+1][lr]=ka.y; Ks[lc+2][lr]=ka.z; Ks[lc+3][lr]=ka.w;
        Ks[lc+16][lr]=kc2.x; Ks[lc+17][lr]=kc2.y; Ks[lc+18][lr]=kc2.z; Ks[lc+19][lr]=kc2.w;
        *(float4*)&Vs[lr][vc] = v0;
        *(float4*)&Vs[lr][vc+4] = v1;
        __syncthreads();

        float s[4][4];
        #pragma unroll
        for (int i = 0; i < 4; i++) {
            float4 z4 = *(const float4*)&zp[(size_t)(q0+(ty<<2)+i)*NSEQ + kb0 + (tx<<2)];
            s[i][0]=z4.x; s[i][1]=z4.y; s[i][2]=z4.z; s[i][3]=z4.w;
        }
        #pragma unroll
        for (int kk = 0; kk < 32; kk++) {
            float4 a4 = *(const float4*)&Qs[kk][ty << 2];
            float4 b4 = *(const float4*)&Ks[kk][tx << 2];
            float ar[4] = {a4.x,a4.y,a4.z,a4.w};
            float br[4] = {b4.x,b4.y,b4.z,b4.w};
            #pragma unroll
            for (int i = 0; i < 4; i++)
                #pragma unroll
                for (int j = 0; j < 4; j++)
                    s[i][j] = fmaf(ar[i], br[j], s[i][j]);
        }
        #pragma unroll
        for (int i = 0; i < 4; i++) {
            float mx = fmaxf(fmaxf(s[i][0],s[i][1]), fmaxf(s[i][2],s[i][3]));
            mx = fmaxf(mx, __shfl_xor_sync(0xffffffffu, mx, 1));
            mx = fmaxf(mx, __shfl_xor_sync(0xffffffffu, mx, 2));
            mx = fmaxf(mx, __shfl_xor_sync(0xffffffffu, mx, 4));
            mx = fmaxf(mx, __shfl_xor_sync(0xffffffffu, mx, 8));
            float mnew = fmaxf(m[i], mx);
            float c = __expf(m[i] - mnew);
            s[i][0] = __expf(s[i][0]-mnew); s[i][1] = __expf(s[i][1]-mnew);
            s[i][2] = __expf(s[i][2]-mnew); s[i][3] = __expf(s[i][3]-mnew);
            float rs = s[i][0]+s[i][1]+s[i][2]+s[i][3];
            rs += __shfl_xor_sync(0xffffffffu, rs, 1);
            rs += __shfl_xor_sync(0xffffffffu, rs, 2);
            rs += __shfl_xor_sync(0xffffffffu, rs, 4);
            rs += __shfl_xor_sync(0xffffffffu, rs, 8);
            l[i] = l[i]*c + rs;
            m[i] = mnew;
            int row = (ty << 2) + i;
            if (tx == 0) { corr_s[row] = c; l_s[row] = l[i]; }
            *(float4*)&Ps[row][tx << 2] = make_float4(s[i][0],s[i][1],s[i][2],s[i][3]);
        }
        __syncthreads();

        float c0 = corr_s[oty*2], c1 = corr_s[oty*2+1];
        #pragma unroll
        for (int j = 0; j < 4; j++) { oacc[0][j] *= c0; oacc[1][j] *= c1; }
        #pragma unroll
        for (int kk = 0; kk < 64; kk++) {
            float p0 = Ps[oty*2][kk];
            float p1 = Ps[oty*2+1][kk];
            float4 vv = *(const float4*)&Vs[kk][otx << 2];
            oacc[0][0]=fmaf(p0,vv.x,oacc[0][0]); oacc[0][1]=fmaf(p0,vv.y,oacc[0][1]);
            oacc[0][2]=fmaf(p0,vv.z,oacc[0][2]); oacc[0][3]=fmaf(p0,vv.w,oacc[0][3]);
            oacc[1][0]=fmaf(p1,vv.x,oacc[1][0]); oacc[1][1]=fmaf(p1,vv.y,oacc[1][1]);
            oacc[1][2]=fmaf(p1,vv.z,oacc[1][2]); oacc[1][3]=fmaf(p1,vv.w,oacc[1][3]);
        }
    }
    float inv0 = 1.f / l_s[oty*2];
    float inv1 = 1.f / l_s[oty*2+1];
    *(float4*)&g_o[(q0 + oty*2 + 0)*DMOD + h*HDIM + (otx << 2)] =
        make_float4(oacc[0][0]*inv0, oacc[0][1]*inv0, oacc[0][2]*inv0, oacc[0][3]*inv0);
    *(float4*)&g_o[(q0 + oty*2 + 1)*DMOD + h*HDIM + (otx << 2)] =
        make_float4(oacc[1][0]*inv1, oacc[1][1]*inv1, oacc[1][2]*inv1, oacc[1][3]*inv1);
}

extern "C" void kernel_launch(void* const* d_in, const int* in_sizes, int n_in,
                              void* d_out, int out_size)
{
    const float* s   = (const float*)d_in[0];
    const float* z   = (const float*)d_in[1];
    const float* nsw = (const float*)d_in[2];
    const float* nsb = (const float*)d_in[3];
    const float* Wq  = (const float*)d_in[4];
    const float* bq  = (const float*)d_in[5];
    const float* Wk  = (const float*)d_in[6];
    const float* Wv  = (const float*)d_in[7];
    const float* Wg  = (const float*)d_in[8];
    const float* zw  = (const float*)d_in[9];
    const float* zb  = (const float*)d_in[10];
    const float* Wz  = (const float*)d_in[11];
    const float* Wo  = (const float*)d_in[12];
    float* out = (float*)d_out;

    prep_kernel<<<1, 256>>>(Wz, zw, zb);
    ln_s_kernel<<<NSEQ, 128>>>(s, nsw, nsb);
    wtrans_kernel<<<dim3(16,16,5), dim3(32,8)>>>(Wq, Wk, Wv, Wg, Wo);
    tc_gemm<<<dim3(8,16,4), 256>>>(bq, nullptr, -1);
    zbias_kernel<<<NN/256, 256>>>(z);
    flash_kernel<<<dim3(NSEQ/64, NHEAD), 256>>>();
    conv_o_kernel<<<NSEQ*DMOD/4/256, 256>>>();
    tc_gemm<<<dim3(8,16,1), 256>>>(bq, out, 4);
}

// round 9
// speedup vs baseline: 1.2488x; 1.0080x over previous
#include <cuda_runtime.h>
#include <cuda_bf16.h>
#include <mma.h>
#include <math.h>
#include <stdint.h>

using namespace nvcuda;

#define NSEQ 1024
#define DMOD 512
#define NHEAD 16
#define HDIM 32
#define DZ 128
#define NN (NSEQ*NSEQ)
#define QSCALE 0.17677669529663687f

typedef unsigned long long u64;
typedef __nv_bfloat16 bf16;

__device__ float g_q[NHEAD*NSEQ*HDIM];
__device__ float g_k[NHEAD*NSEQ*HDIM];
__device__ float g_v[NHEAD*NSEQ*HDIM];
__device__ float g_gate[NSEQ*DMOD];
__device__ float g_o[NSEQ*DMOD];
__device__ float g_scores[NHEAD*NN];
__device__ float g_wzp[DZ*NHEAD];
__device__ float g_alpha[NHEAD];
__device__ float g_beta[NHEAD];
__device__ bf16 g_sa_hi[NSEQ*DMOD], g_sa_lo[NSEQ*DMOD];
__device__ bf16 g_oa_hi[NSEQ*DMOD], g_oa_lo[NSEQ*DMOD];
__device__ bf16 g_wt_hi[5*DMOD*DMOD], g_wt_lo[5*DMOD*DMOD];

__global__ void prep_kernel(const float* __restrict__ Wz,
                            const float* __restrict__ zw,
                            const float* __restrict__ zb)
{
    int t = threadIdx.x;
    for (int i = t; i < DZ*NHEAD; i += blockDim.x)
        g_wzp[i] = zw[i >> 4] * Wz[i];
    if (t < NHEAD) {
        float a = 0.f, b = 0.f;
        for (int c = 0; c < DZ; c++) {
            float wv = Wz[c*NHEAD + t];
            a += zw[c] * wv;
            b += zb[c] * wv;
        }
        g_alpha[t] = a;
        g_beta[t]  = b;
    }
}

__global__ __launch_bounds__(128) void ln_s_kernel(const float* __restrict__ s,
                                                   const float* __restrict__ w,
                                                   const float* __restrict__ b)
{
    __shared__ float sred[8];
    __shared__ float s_mu, s_rstd;
    int row = blockIdx.x, tid = threadIdx.x;
    float4 v = *(const float4*)&s[row*DMOD + tid*4];
    float sum = v.x + v.y + v.z + v.w;
    float ssq = v.x*v.x + v.y*v.y + v.z*v.z + v.w*v.w;
    #pragma unroll
    for (int o = 16; o; o >>= 1) {
        sum += __shfl_xor_sync(0xffffffffu, sum, o);
        ssq += __shfl_xor_sync(0xffffffffu, ssq, o);
    }
    int lane = tid & 31, wid = tid >> 5;
    if (lane == 0) { sred[wid] = sum; sred[4 + wid] = ssq; }
    __syncthreads();
    if (tid == 0) {
        float a = sred[0]+sred[1]+sred[2]+sred[3];
        float q = sred[4]+sred[5]+sred[6]+sred[7];
        float mu = a * (1.f/DMOD);
        float var = q * (1.f/DMOD) - mu*mu;
        s_mu = mu; s_rstd = rsqrtf(var + 1e-5f);
    }
    __syncthreads();
    float mu = s_mu, rstd = s_rstd;
    float4 wv = *(const float4*)&w[tid*4];
    float4 bv = *(const float4*)&b[tid*4];
    float o4[4];
    o4[0] = (v.x-mu)*rstd*wv.x + bv.x;
    o4[1] = (v.y-mu)*rstd*wv.y + bv.y;
    o4[2] = (v.z-mu)*rstd*wv.z + bv.z;
    o4[3] = (v.w-mu)*rstd*wv.w + bv.w;
    union { bf16 h[4]; uint2 u; } H, L;
    #pragma unroll
    for (int j = 0; j < 4; j++) {
        H.h[j] = __float2bfloat16(o4[j]);
        L.h[j] = __float2bfloat16(o4[j] - __bfloat162float(H.h[j]));
    }
    int idx = row*DMOD + tid*4;
    *(uint2*)&g_sa_hi[idx] = H.u;
    *(uint2*)&g_sa_lo[idx] = L.u;
}

// transpose + bf16-split weights: g_wt[g][n][k] = W_g[k][n]
__global__ void wtrans_kernel(const float* __restrict__ Wq, const float* __restrict__ Wk,
                              const float* __restrict__ Wv, const float* __restrict__ Wg,
                              const float* __restrict__ Wo)
{
    __shared__ float t[32][33];
    int g = blockIdx.z;
    const float* W = (g==0)?Wq:(g==1)?Wk:(g==2)?Wv:(g==3)?Wg:Wo;
    int tx = threadIdx.x, ty = threadIdx.y;
    int bx = blockIdx.x*32, by = blockIdx.y*32;
    #pragma unroll
    for (int i = 0; i < 4; i++)
        t[ty + 8*i][tx] = W[(size_t)(by + ty + 8*i)*DMOD + bx + tx];
    __syncthreads();
    size_t base = (size_t)g*DMOD*DMOD;
    #pragma unroll
    for (int i = 0; i < 4; i++) {
        int n = bx + ty + 8*i, k = by + tx;
        float v = t[tx][ty + 8*i];
        bf16 h = __float2bfloat16(v);
        g_wt_hi[base + (size_t)n*DMOD + k] = h;
        g_wt_lo[base + (size_t)n*DMOD + k] = __float2bfloat16(v - __bfloat162float(h));
    }
}

__global__ __launch_bounds__(256) void conv_o_kernel()
{
    int idx = (blockIdx.x*256 + threadIdx.x)*4;
    float4 o = *(const float4*)&g_o[idx];
    float4 g = *(const float4*)&g_gate[idx];
    float v[4] = {o.x*g.x, o.y*g.y, o.z*g.z, o.w*g.w};
    union { bf16 h[4]; uint2 u; } H, L;
    #pragma unroll
    for (int j = 0; j < 4; j++) {
        H.h[j] = __float2bfloat16(v[j]);
        L.h[j] = __float2bfloat16(v[j] - __bfloat162float(H.h[j]));
    }
    *(uint2*)&g_oa_hi[idx] = H.u;
    *(uint2*)&g_oa_lo[idx] = L.u;
}

// WMMA bf16-split GEMM. CTA tile 64x64, 8 warps of 16x32, K chunks of 64.
__global__ __launch_bounds__(256) void tc_gemm(const float* __restrict__ bq,
                                               float* __restrict__ Cout, int mode_sel)
{
    __shared__ __align__(16) char smbuf[4*64*72*2];
    bf16* Ah_s = (bf16*)smbuf;
    bf16* Al_s = Ah_s + 64*72;
    bf16* Bh_s = Al_s + 64*72;
    bf16* Bl_s = Bh_s + 64*72;
    float* Cs  = (float*)smbuf;

    int mode = (mode_sel < 0) ? (int)blockIdx.z : mode_sel;
    const bf16* Ah = (mode==4) ? g_oa_hi : g_sa_hi;
    const bf16* Al = (mode==4) ? g_oa_lo : g_sa_lo;
    size_t wb = (size_t)((mode==4)?4:mode)*DMOD*DMOD;
    const bf16* Bh = g_wt_hi + wb;
    const bf16* Bl = g_wt_lo + wb;

    int tid = threadIdx.x;
    int w = tid >> 5, wr = w >> 1, wc = w & 1;
    int m0 = blockIdx.y*64, n0 = blockIdx.x*64;
    int lrow = tid >> 2, lseg = (tid & 3) << 4;

    wmma::fragment<wmma::accumulator,16,16,16,float> acc[2];
    wmma::fill_fragment(acc[0], 0.f);
    wmma::fill_fragment(acc[1], 0.f);

    const bf16* gAh = Ah + (size_t)(m0+lrow)*DMOD + lseg;
    const bf16* gAl = Al + (size_t)(m0+lrow)*DMOD + lseg;
    const bf16* gBh = Bh + (size_t)(n0+lrow)*DMOD + lseg;
    const bf16* gBl = Bl + (size_t)(n0+lrow)*DMOD + lseg;
    int soff = lrow*72 + lseg;

    for (int ch = 0; ch < 8; ch++) {
        uint4 a0 = *(const uint4*)(gAh + ch*64);
        uint4 a1 = *(const uint4*)(gAh + ch*64 + 8);
        uint4 a2 = *(const uint4*)(gAl + ch*64);
        uint4 a3 = *(const uint4*)(gAl + ch*64 + 8);
        uint4 b0 = *(const uint4*)(gBh + ch*64);
        uint4 b1 = *(const uint4*)(gBh + ch*64 + 8);
        uint4 b2 = *(const uint4*)(gBl + ch*64);
        uint4 b3 = *(const uint4*)(gBl + ch*64 + 8);
        if (ch) __syncthreads();
        *(uint4*)(Ah_s + soff)     = a0;
        *(uint4*)(Ah_s + soff + 8) = a1;
        *(uint4*)(Al_s + soff)     = a2;
        *(uint4*)(Al_s + soff + 8) = a3;
        *(uint4*)(Bh_s + soff)     = b0;
        *(uint4*)(Bh_s + soff + 8) = b1;
        *(uint4*)(Bl_s + soff)     = b2;
        *(uint4*)(Bl_s + soff + 8) = b3;
        __syncthreads();
        #pragma unroll
        for (int ks = 0; ks < 4; ks++) {
            wmma::fragment<wmma::matrix_a,16,16,16,bf16,wmma::row_major> fah, fal;
            wmma::load_matrix_sync(fah, Ah_s + (wr*16)*72 + ks*16, 72);
            wmma::load_matrix_sync(fal, Al_s + (wr*16)*72 + ks*16, 72);
            #pragma unroll
            for (int c = 0; c < 2; c++) {
                wmma::fragment<wmma::matrix_b,16,16,16,bf16,wmma::col_major> fbh, fbl;
                wmma::load_matrix_sync(fbh, Bh_s + (wc*32 + c*16)*72 + ks*16, 72);
                wmma::load_matrix_sync(fbl, Bl_s + (wc*32 + c*16)*72 + ks*16, 72);
                wmma::mma_sync(acc[c], fah, fbh, acc[c]);
                wmma::mma_sync(acc[c], fah, fbl, acc[c]);
                wmma::mma_sync(acc[c], fal, fbh, acc[c]);
            }
        }
    }
    __syncthreads();
    wmma::store_matrix_sync(Cs + (wr*16)*72 + wc*32,      acc[0], 72, wmma::mem_row_major);
    wmma::store_matrix_sync(Cs + (wr*16)*72 + wc*32 + 16, acc[1], 72, wmma::mem_row_major);
    __syncthreads();

    int r = lrow;
    int colg = n0 + lseg;
    if (mode <= 2) {
        float* dst = (mode==0) ? g_q : (mode==1 ? g_k : g_v);
        float* dp = &dst[((size_t)(colg >> 5)*NSEQ + m0 + r)*HDIM + (colg & 31)];
        #pragma unroll
        for (int j = 0; j < 4; j++) {
            float4 v = *(float4*)&Cs[r*72 + lseg + j*4];
            if (mode == 0) {
                float4 bb = *(const float4*)&bq[colg + j*4];
                v.x = (v.x + bb.x)*QSCALE; v.y = (v.y + bb.y)*QSCALE;
                v.z = (v.z + bb.z)*QSCALE; v.w = (v.w + bb.w)*QSCALE;
            }
            *(float4*)&dp[j*4] = v;
        }
    } else if (mode == 3) {
        float* dp = &g_gate[(size_t)(m0 + r)*DMOD + colg];
        #pragma unroll
        for (int j = 0; j < 4; j++) {
            float4 v = *(float4*)&Cs[r*72 + lseg + j*4];
            v.x = 1.f/(1.f + __expf(-v.x)); v.y = 1.f/(1.f + __expf(-v.y));
            v.z = 1.f/(1.f + __expf(-v.z)); v.w = 1.f/(1.f + __expf(-v.w));
            *(float4*)&dp[j*4] = v;
        }
    } else {
        float* dp = &Cout[(size_t)(m0 + r)*DMOD + colg];
        #pragma unroll
        for (int j = 0; j < 4; j++)
            *(float4*)&dp[j*4] = *(float4*)&Cs[r*72 + lseg + j*4];
    }
}

// fused LN(z)@Wz on tensor cores: per warp 32 rows; z copied row-major to smem
// with bf16 hi/lo split (no transpose); 12 HMMA per 32-col chunk; stats from
// one own-row re-read; epilogue applies rstd and stores [h][row] coalesced.
__global__ __launch_bounds__(256) void zbias_kernel(const float* __restrict__ z)
{
    __shared__ __align__(16) bf16 wzh[DZ][16];          // 4 KB
    __shared__ __align__(16) bf16 wzl[DZ][16];          // 4 KB
    __shared__ __align__(16) bf16 ztile[8][2][32][40];  // 40 KB
    int tid = threadIdx.x, lane = tid & 31, w = tid >> 5;

    for (int i = tid; i < DZ*NHEAD; i += 256) {
        float v = g_wzp[i];
        bf16 h = __float2bfloat16(v);
        wzh[i >> 4][i & 15] = h;
        wzl[i >> 4][i & 15] = __float2bfloat16(v - __bfloat162float(h));
    }
    __syncthreads();

    int row0w = blockIdx.x*256 + w*32;
    const float* zwarp = z + (size_t)row0w*DZ;
    int lr8 = lane >> 3, lc8 = (lane & 7) << 2;

    wmma::fragment<wmma::accumulator,16,16,16,float> acc[2];
    wmma::fill_fragment(acc[0], 0.f);
    wmma::fill_fragment(acc[1], 0.f);
    float sum = 0.f, ssq = 0.f;

    bf16 (*zh)[40] = ztile[w][0];
    bf16 (*zl)[40] = ztile[w][1];

    for (int ch = 0; ch < 4; ch++) {
        #pragma unroll
        for (int j = 0; j < 8; j++) {
            float4 v = *(const float4*)&zwarp[(size_t)(j*4 + lr8)*DZ + ch*32 + lc8];
            union { bf16 h[4]; uint2 u; } H, L;
            float vr[4] = {v.x, v.y, v.z, v.w};
            #pragma unroll
            for (int e = 0; e < 4; e++) {
                H.h[e] = __float2bfloat16(vr[e]);
                L.h[e] = __float2bfloat16(vr[e] - __bfloat162float(H.h[e]));
            }
            *(uint2*)&zh[j*4 + lr8][lc8] = H.u;
            *(uint2*)&zl[j*4 + lr8][lc8] = L.u;
        }
        __syncwarp();
        // stats over own row (reconstruct z = hi + lo)
        #pragma unroll
        for (int c8 = 0; c8 < 4; c8++) {
            union { bf16 h[8]; uint4 u; } Hv, Lv;
            Hv.u = *(const uint4*)&zh[lane][c8*8];
            Lv.u = *(const uint4*)&zl[lane][c8*8];
            #pragma unroll
            for (int e = 0; e < 8; e++) {
                float zv = __bfloat162float(Hv.h[e]) + __bfloat162float(Lv.h[e]);
                sum += zv;
                ssq = fmaf(zv, zv, ssq);
            }
        }
        // 12 MMAs: 2 row-tiles x 2 k-tiles x 3 error-split products
        #pragma unroll
        for (int kt = 0; kt < 2; kt++) {
            wmma::fragment<wmma::matrix_b,16,16,16,bf16,wmma::row_major> fbh, fbl;
            wmma::load_matrix_sync(fbh, &wzh[ch*32 + kt*16][0], 16);
            wmma::load_matrix_sync(fbl, &wzl[ch*32 + kt*16][0], 16);
            #pragma unroll
            for (int rt = 0; rt < 2; rt++) {
                wmma::fragment<wmma::matrix_a,16,16,16,bf16,wmma::row_major> fah, fal;
                wmma::load_matrix_sync(fah, &zh[rt*16][kt*16], 40);
                wmma::load_matrix_sync(fal, &zl[rt*16][kt*16], 40);
                wmma::mma_sync(acc[rt], fah, fbh, acc[rt]);
                wmma::mma_sync(acc[rt], fah, fbl, acc[rt]);
                wmma::mma_sync(acc[rt], fal, fbh, acc[rt]);
            }
        }
        __syncwarp();
    }

    float* Cs = (float*)ztile[w];
    wmma::store_matrix_sync(Cs,          acc[0], 20, wmma::mem_row_major);
    wmma::store_matrix_sync(Cs + 16*20,  acc[1], 20, wmma::mem_row_major);
    __syncwarp();

    float mu = sum * (1.f/DZ);
    float var = ssq * (1.f/DZ) - mu*mu;
    float rstd = rsqrtf(var + 1e-5f);
    int row = row0w + lane;
    #pragma unroll
    for (int h = 0; h < NHEAD; h++) {
        float a = Cs[lane*20 + h];
        g_scores[(size_t)h*NN + row] = rstd*(a - mu*g_alpha[h]) + g_beta[h];
    }
}

// Flash attention: one block per (q-tile 64, head). S=QK^T+zb, online softmax, O=P@V.
__global__ __launch_bounds__(256) void flash_kernel()
{
    __shared__ float Qs[32][68];
    __shared__ float Ks[32][68];
    __shared__ float Vs[64][36];
    __shared__ float Ps[64][68];
    __shared__ float corr_s[64];
    __shared__ float l_s[64];
    int tid = threadIdx.x;
    int h = blockIdx.y, q0 = blockIdx.x*64;
    const float* qb = g_q + h*NSEQ*HDIM;
    const float* kp = g_k + h*NSEQ*HDIM;
    const float* vp = g_v + h*NSEQ*HDIM;
    const float* zp = g_scores + (size_t)h*NN;

    int lr = tid >> 2;
    int lc = (tid & 3) << 2;
    {
        float4 a = *(const float4*)&qb[(q0+lr)*HDIM + lc];
        float4 b = *(const float4*)&qb[(q0+lr)*HDIM + lc + 16];
        Qs[lc+0][lr]=a.x; Qs[lc+1][lr]=a.y; Qs[lc+2][lr]=a.z; Qs[lc+3][lr]=a.w;
        Qs[lc+16][lr]=b.x; Qs[lc+17][lr]=b.y; Qs[lc+18][lr]=b.z; Qs[lc+19][lr]=b.w;
    }
    int tx = tid & 15, ty = tid >> 4;
    int oty = tid >> 3, otx = tid & 7;
    int vc = (tid & 3) << 3;
    float m[4], l[4];
    #pragma unroll
    for (int i = 0; i < 4; i++) { m[i] = -1e30f; l[i] = 0.f; }
    float oacc[2][4] = {};

    for (int kb0 = 0; kb0 < NSEQ; kb0 += 64) {
        float4 ka = *(const float4*)&kp[(kb0+lr)*HDIM + lc];
        float4 kc2 = *(const float4*)&kp[(kb0+lr)*HDIM + lc + 16];
        float4 v0 = *(const float4*)&vp[(kb0+lr)*HDIM + vc];
        float4 v1 = *(const float4*)&vp[(kb0+lr)*HDIM + vc + 4];
        __syncthreads();
        Ks[lc+0][lr]=ka.x; Ks[lc+1][lr]=ka.y; Ks[lc+2][lr]=ka.z; Ks[lc+3][lr]=ka.w;
        Ks[lc+16][lr]=kc2.x; Ks[lc+17][lr]=kc2.y; Ks[lc+18][lr]=kc2.z; Ks[lc+19][lr]=kc2.w;
        *(float4*)&Vs[lr][vc] = v0;
        *(float4*)&Vs[lr][vc+4] = v1;
        __syncthreads();

        float s[4][4];
        #pragma unroll
        for (int i = 0; i < 4; i++) {
            float4 z4 = *(const float4*)&zp[(size_t)(q0+(ty<<2)+i)*NSEQ + kb0 + (tx<<2)];
            s[i][0]=z4.x; s[i][1]=z4.y; s[i][2]=z4.z; s[i][3]=z4.w;
        }
        #pragma unroll
        for (int kk = 0; kk < 32; kk++) {
            float4 a4 = *(const float4*)&Qs[kk][ty << 2];
            float4 b4 = *(const float4*)&Ks[kk][tx << 2];
            float ar[4] = {a4.x,a4.y,a4.z,a4.w};
            float br[4] = {b4.x,b4.y,b4.z,b4.w};
            #pragma unroll
            for (int i = 0; i < 4; i++)
                #pragma unroll
                for (int j = 0; j < 4; j++)
                    s[i][j] = fmaf(ar[i], br[j], s[i][j]);
        }
        #pragma unroll
        for (int i = 0; i < 4; i++) {
            float mx = fmaxf(fmaxf(s[i][0],s[i][1]), fmaxf(s[i][2],s[i][3]));
            mx = fmaxf(mx, __shfl_xor_sync(0xffffffffu, mx, 1));
            mx = fmaxf(mx, __shfl_xor_sync(0xffffffffu, mx, 2));
            mx = fmaxf(mx, __shfl_xor_sync(0xffffffffu, mx, 4));
            mx = fmaxf(mx, __shfl_xor_sync(0xffffffffu, mx, 8));
            float mnew = fmaxf(m[i], mx);
            float c = __expf(m[i] - mnew);
            s[i][0] = __expf(s[i][0]-mnew); s[i][1] = __expf(s[i][1]-mnew);
            s[i][2] = __expf(s[i][2]-mnew); s[i][3] = __expf(s[i][3]-mnew);
            float rs = s[i][0]+s[i][1]+s[i][2]+s[i][3];
            rs += __shfl_xor_sync(0xffffffffu, rs, 1);
            rs += __shfl_xor_sync(0xffffffffu, rs, 2);
            rs += __shfl_xor_sync(0xffffffffu, rs, 4);
            rs += __shfl_xor_sync(0xffffffffu, rs, 8);
            l[i] = l[i]*c + rs;
            m[i] = mnew;
            int row = (ty << 2) + i;
            if (tx == 0) { corr_s[row] = c; l_s[row] = l[i]; }
            *(float4*)&Ps[row][tx << 2] = make_float4(s[i][0],s[i][1],s[i][2],s[i][3]);
        }
        __syncthreads();

        float c0 = corr_s[oty*2], c1 = corr_s[oty*2+1];
        #pragma unroll
        for (int j = 0; j < 4; j++) { oacc[0][j] *= c0; oacc[1][j] *= c1; }
        #pragma unroll
        for (int kk = 0; kk < 64; kk++) {
            float p0 = Ps[oty*2][kk];
            float p1 = Ps[oty*2+1][kk];
            float4 vv = *(const float4*)&Vs[kk][otx << 2];
            oacc[0][0]=fmaf(p0,vv.x,oacc[0][0]); oacc[0][1]=fmaf(p0,vv.y,oacc[0][1]);
            oacc[0][2]=fmaf(p0,vv.z,oacc[0][2]); oacc[0][3]=fmaf(p0,vv.w,oacc[0][3]);
            oacc[1][0]=fmaf(p1,vv.x,oacc[1][0]); oacc[1][1]=fmaf(p1,vv.y,oacc[1][1]);
            oacc[1][2]=fmaf(p1,vv.z,oacc[1][2]); oacc[1][3]=fmaf(p1,vv.w,oacc[1][3]);
        }
    }
    float inv0 = 1.f / l_s[oty*2];
    float inv1 = 1.f / l_s[oty*2+1];
    *(float4*)&g_o[(q0 + oty*2 + 0)*DMOD + h*HDIM + (otx << 2)] =
        make_float4(oacc[0][0]*inv0, oacc[0][1]*inv0, oacc[0][2]*inv0, oacc[0][3]*inv0);
    *(float4*)&g_o[(q0 + oty*2 + 1)*DMOD + h*HDIM + (otx << 2)] =
        make_float4(oacc[1][0]*inv1, oacc[1][1]*inv1, oacc[1][2]*inv1, oacc[1][3]*inv1);
}

extern "C" void kernel_launch(void* const* d_in, const int* in_sizes, int n_in,
                              void* d_out, int out_size)
{
    const float* s   = (const float*)d_in[0];
    const float* z   = (const float*)d_in[1];
    const float* nsw = (const float*)d_in[2];
    const float* nsb = (const float*)d_in[3];
    const float* Wq  = (const float*)d_in[4];
    const float* bq  = (const float*)d_in[5];
    const float* Wk  = (const float*)d_in[6];
    const float* Wv  = (const float*)d_in[7];
    const float* Wg  = (const float*)d_in[8];
    const float* zw  = (const float*)d_in[9];
    const float* zb  = (const float*)d_in[10];
    const float* Wz  = (const float*)d_in[11];
    const float* Wo  = (const float*)d_in[12];
    float* out = (float*)d_out;

    prep_kernel<<<1, 256>>>(Wz, zw, zb);
    ln_s_kernel<<<NSEQ, 128>>>(s, nsw, nsb);
    wtrans_kernel<<<dim3(16,16,5), dim3(32,8)>>>(Wq, Wk, Wv, Wg, Wo);
    tc_gemm<<<dim3(8,16,4), 256>>>(bq, nullptr, -1);
    zbias_kernel<<<NN/256, 256>>>(z);
    flash_kernel<<<dim3(NSEQ/64, NHEAD), 256>>>();
    conv_o_kernel<<<NSEQ*DMOD/4/256, 256>>>();
    tc_gemm<<<dim3(8,16,1), 256>>>(bq, out, 4);
}

// round 10
// speedup vs baseline: 1.2648x; 1.0128x over previous
#include <cuda_runtime.h>
#include <cuda_bf16.h>
#include <mma.h>
#include <math.h>
#include <stdint.h>

using namespace nvcuda;

#define NSEQ 1024
#define DMOD 512
#define NHEAD 16
#define HDIM 32
#define DZ 128
#define NN (NSEQ*NSEQ)
#define QSCALE 0.17677669529663687f

typedef unsigned long long u64;
typedef __nv_bfloat16 bf16;

__device__ float g_q[NHEAD*NSEQ*HDIM];
__device__ float g_k[NHEAD*NSEQ*HDIM];
__device__ float g_v[NHEAD*NSEQ*HDIM];
__device__ float g_gate[NSEQ*DMOD];
__device__ float g_o[NSEQ*DMOD];
__device__ float g_scores[NHEAD*NN];
__device__ float g_wzp[DZ*NHEAD];
__device__ float g_alpha[NHEAD];
__device__ float g_beta[NHEAD];
__device__ bf16 g_sa_hi[NSEQ*DMOD], g_sa_lo[NSEQ*DMOD];
__device__ bf16 g_oa_hi[NSEQ*DMOD], g_oa_lo[NSEQ*DMOD];
__device__ bf16 g_wt_hi[5*DMOD*DMOD], g_wt_lo[5*DMOD*DMOD];

__device__ __forceinline__ uint32_t s2u(const void* p) {
    uint32_t a;
    asm("{ .reg .u64 t; cvta.to.shared.u64 t, %1; cvt.u32.u64 %0, t; }" : "=r"(a) : "l"(p));
    return a;
}
__device__ __forceinline__ void cp16(void* smem, const void* g) {
    asm volatile("cp.async.cg.shared.global [%0], [%1], 16;"
                 :: "r"(s2u(smem)), "l"(g) : "memory");
}
__device__ __forceinline__ void cp_commit() {
    asm volatile("cp.async.commit_group;" ::: "memory");
}

__global__ void prep_kernel(const float* __restrict__ Wz,
                            const float* __restrict__ zw,
                            const float* __restrict__ zb)
{
    int t = threadIdx.x;
    for (int i = t; i < DZ*NHEAD; i += blockDim.x)
        g_wzp[i] = zw[i >> 4] * Wz[i];
    if (t < NHEAD) {
        float a = 0.f, b = 0.f;
        for (int c = 0; c < DZ; c++) {
            float wv = Wz[c*NHEAD + t];
            a += zw[c] * wv;
            b += zb[c] * wv;
        }
        g_alpha[t] = a;
        g_beta[t]  = b;
    }
}

__global__ __launch_bounds__(128) void ln_s_kernel(const float* __restrict__ s,
                                                   const float* __restrict__ w,
                                                   const float* __restrict__ b)
{
    __shared__ float sred[8];
    __shared__ float s_mu, s_rstd;
    int row = blockIdx.x, tid = threadIdx.x;
    float4 v = *(const float4*)&s[row*DMOD + tid*4];
    float sum = v.x + v.y + v.z + v.w;
    float ssq = v.x*v.x + v.y*v.y + v.z*v.z + v.w*v.w;
    #pragma unroll
    for (int o = 16; o; o >>= 1) {
        sum += __shfl_xor_sync(0xffffffffu, sum, o);
        ssq += __shfl_xor_sync(0xffffffffu, ssq, o);
    }
    int lane = tid & 31, wid = tid >> 5;
    if (lane == 0) { sred[wid] = sum; sred[4 + wid] = ssq; }
    __syncthreads();
    if (tid == 0) {
        float a = sred[0]+sred[1]+sred[2]+sred[3];
        float q = sred[4]+sred[5]+sred[6]+sred[7];
        float mu = a * (1.f/DMOD);
        float var = q * (1.f/DMOD) - mu*mu;
        s_mu = mu; s_rstd = rsqrtf(var + 1e-5f);
    }
    __syncthreads();
    float mu = s_mu, rstd = s_rstd;
    float4 wv = *(const float4*)&w[tid*4];
    float4 bv = *(const float4*)&b[tid*4];
    float o4[4];
    o4[0] = (v.x-mu)*rstd*wv.x + bv.x;
    o4[1] = (v.y-mu)*rstd*wv.y + bv.y;
    o4[2] = (v.z-mu)*rstd*wv.z + bv.z;
    o4[3] = (v.w-mu)*rstd*wv.w + bv.w;
    union { bf16 h[4]; uint2 u; } H, L;
    #pragma unroll
    for (int j = 0; j < 4; j++) {
        H.h[j] = __float2bfloat16(o4[j]);
        L.h[j] = __float2bfloat16(o4[j] - __bfloat162float(H.h[j]));
    }
    int idx = row*DMOD + tid*4;
    *(uint2*)&g_sa_hi[idx] = H.u;
    *(uint2*)&g_sa_lo[idx] = L.u;
}

__global__ void wtrans_kernel(const float* __restrict__ Wq, const float* __restrict__ Wk,
                              const float* __restrict__ Wv, const float* __restrict__ Wg,
                              const float* __restrict__ Wo)
{
    __shared__ float t[32][33];
    int g = blockIdx.z;
    const float* W = (g==0)?Wq:(g==1)?Wk:(g==2)?Wv:(g==3)?Wg:Wo;
    int tx = threadIdx.x, ty = threadIdx.y;
    int bx = blockIdx.x*32, by = blockIdx.y*32;
    #pragma unroll
    for (int i = 0; i < 4; i++)
        t[ty + 8*i][tx] = W[(size_t)(by + ty + 8*i)*DMOD + bx + tx];
    __syncthreads();
    size_t base = (size_t)g*DMOD*DMOD;
    #pragma unroll
    for (int i = 0; i < 4; i++) {
        int n = bx + ty + 8*i, k = by + tx;
        float v = t[tx][ty + 8*i];
        bf16 h = __float2bfloat16(v);
        g_wt_hi[base + (size_t)n*DMOD + k] = h;
        g_wt_lo[base + (size_t)n*DMOD + k] = __float2bfloat16(v - __bfloat162float(h));
    }
}

__global__ __launch_bounds__(256) void conv_o_kernel()
{
    int idx = (blockIdx.x*256 + threadIdx.x)*4;
    float4 o = *(const float4*)&g_o[idx];
    float4 g = *(const float4*)&g_gate[idx];
    float v[4] = {o.x*g.x, o.y*g.y, o.z*g.z, o.w*g.w};
    union { bf16 h[4]; uint2 u; } H, L;
    #pragma unroll
    for (int j = 0; j < 4; j++) {
        H.h[j] = __float2bfloat16(v[j]);
        L.h[j] = __float2bfloat16(v[j] - __bfloat162float(H.h[j]));
    }
    *(uint2*)&g_oa_hi[idx] = H.u;
    *(uint2*)&g_oa_lo[idx] = L.u;
}

// WMMA bf16-split GEMM with 2-stage cp.async pipeline.
// CTA tile 64x64, 8 warps of 16x32, K chunks of 64, dynamic smem 72KB.
__global__ __launch_bounds__(256) void tc_gemm(const float* __restrict__ bq,
                                               float* __restrict__ Cout, int mode_sel)
{
    extern __shared__ __align__(16) char dynsm[];
    const int STAGE = 64*72*2;       // bytes per array
    float* Cs = (float*)dynsm;

    int mode = (mode_sel < 0) ? (int)blockIdx.z : mode_sel;
    const bf16* Ah = (mode==4) ? g_oa_hi : g_sa_hi;
    const bf16* Al = (mode==4) ? g_oa_lo : g_sa_lo;
    size_t wb = (size_t)((mode==4)?4:mode)*DMOD*DMOD;
    const bf16* Bh = g_wt_hi + wb;
    const bf16* Bl = g_wt_lo + wb;

    int tid = threadIdx.x;
    int w = tid >> 5, wr = w >> 1, wc = w & 1;
    int m0 = blockIdx.y*64, n0 = blockIdx.x*64;
    int lrow = tid >> 2, lseg = (tid & 3) << 4;

    wmma::fragment<wmma::accumulator,16,16,16,float> acc[2];
    wmma::fill_fragment(acc[0], 0.f);
    wmma::fill_fragment(acc[1], 0.f);

    const bf16* gAh = Ah + (size_t)(m0+lrow)*DMOD + lseg;
    const bf16* gAl = Al + (size_t)(m0+lrow)*DMOD + lseg;
    const bf16* gBh = Bh + (size_t)(n0+lrow)*DMOD + lseg;
    const bf16* gBl = Bl + (size_t)(n0+lrow)*DMOD + lseg;
    int soff = (lrow*72 + lseg)*2;   // byte offset within an array

    auto issue = [&](int ch, int st) {
        char* base = dynsm + st*4*STAGE;
        cp16(base + 0*STAGE + soff,      gAh + ch*64);
        cp16(base + 0*STAGE + soff + 16, gAh + ch*64 + 8);
        cp16(base + 1*STAGE + soff,      gAl + ch*64);
        cp16(base + 1*STAGE + soff + 16, gAl + ch*64 + 8);
        cp16(base + 2*STAGE + soff,      gBh + ch*64);
        cp16(base + 2*STAGE + soff + 16, gBh + ch*64 + 8);
        cp16(base + 3*STAGE + soff,      gBl + ch*64);
        cp16(base + 3*STAGE + soff + 16, gBl + ch*64 + 8);
        cp_commit();
    };

    issue(0, 0);
    for (int ch = 0; ch < 8; ch++) {
        int st = ch & 1;
        if (ch < 7) issue(ch+1, st^1);
        if (ch < 7) asm volatile("cp.async.wait_group 1;" ::: "memory");
        else        asm volatile("cp.async.wait_group 0;" ::: "memory");
        __syncthreads();
        bf16* Ah_s = (bf16*)(dynsm + st*4*STAGE + 0*STAGE);
        bf16* Al_s = (bf16*)(dynsm + st*4*STAGE + 1*STAGE);
        bf16* Bh_s = (bf16*)(dynsm + st*4*STAGE + 2*STAGE);
        bf16* Bl_s = (bf16*)(dynsm + st*4*STAGE + 3*STAGE);
        #pragma unroll
        for (int ks = 0; ks < 4; ks++) {
            wmma::fragment<wmma::matrix_a,16,16,16,bf16,wmma::row_major> fah, fal;
            wmma::load_matrix_sync(fah, Ah_s + (wr*16)*72 + ks*16, 72);
            wmma::load_matrix_sync(fal, Al_s + (wr*16)*72 + ks*16, 72);
            #pragma unroll
            for (int c = 0; c < 2; c++) {
                wmma::fragment<wmma::matrix_b,16,16,16,bf16,wmma::col_major> fbh, fbl;
                wmma::load_matrix_sync(fbh, Bh_s + (wc*32 + c*16)*72 + ks*16, 72);
                wmma::load_matrix_sync(fbl, Bl_s + (wc*32 + c*16)*72 + ks*16, 72);
                wmma::mma_sync(acc[c], fah, fbh, acc[c]);
                wmma::mma_sync(acc[c], fah, fbl, acc[c]);
                wmma::mma_sync(acc[c], fal, fbh, acc[c]);
            }
        }
        __syncthreads();
    }
    wmma::store_matrix_sync(Cs + (wr*16)*72 + wc*32,      acc[0], 72, wmma::mem_row_major);
    wmma::store_matrix_sync(Cs + (wr*16)*72 + wc*32 + 16, acc[1], 72, wmma::mem_row_major);
    __syncthreads();

    int r = lrow;
    int colg = n0 + lseg;
    if (mode <= 2) {
        float* dst = (mode==0) ? g_q : (mode==1 ? g_k : g_v);
        float* dp = &dst[((size_t)(colg >> 5)*NSEQ + m0 + r)*HDIM + (colg & 31)];
        #pragma unroll
        for (int j = 0; j < 4; j++) {
            float4 v = *(float4*)&Cs[r*72 + lseg + j*4];
            if (mode == 0) {
                float4 bb = *(const float4*)&bq[colg + j*4];
                v.x = (v.x + bb.x)*QSCALE; v.y = (v.y + bb.y)*QSCALE;
                v.z = (v.z + bb.z)*QSCALE; v.w = (v.w + bb.w)*QSCALE;
            }
            *(float4*)&dp[j*4] = v;
        }
    } else if (mode == 3) {
        float* dp = &g_gate[(size_t)(m0 + r)*DMOD + colg];
        #pragma unroll
        for (int j = 0; j < 4; j++) {
            float4 v = *(float4*)&Cs[r*72 + lseg + j*4];
            v.x = 1.f/(1.f + __expf(-v.x)); v.y = 1.f/(1.f + __expf(-v.y));
            v.z = 1.f/(1.f + __expf(-v.z)); v.w = 1.f/(1.f + __expf(-v.w));
            *(float4*)&dp[j*4] = v;
        }
    } else {
        float* dp = &Cout[(size_t)(m0 + r)*DMOD + colg];
        #pragma unroll
        for (int j = 0; j < 4; j++)
            *(float4*)&dp[j*4] = *(float4*)&Cs[r*72 + lseg + j*4];
    }
}

// fused LN(z)@Wz on tensor cores, v3: stats in registers during split
// (shuffle-reduced, no smem re-read) + register prefetch of next chunk.
__global__ __launch_bounds__(256) void zbias_kernel(const float* __restrict__ z)
{
    __shared__ __align__(16) bf16 wzh[DZ][16];          // 4 KB
    __shared__ __align__(16) bf16 wzl[DZ][16];          // 4 KB
    __shared__ __align__(16) bf16 ztile[8][2][32][40];  // 40 KB
    int tid = threadIdx.x, lane = tid & 31, w = tid >> 5;

    for (int i = tid; i < DZ*NHEAD; i += 256) {
        float v = g_wzp[i];
        bf16 h = __float2bfloat16(v);
        wzh[i >> 4][i & 15] = h;
        wzl[i >> 4][i & 15] = __float2bfloat16(v - __bfloat162float(h));
    }
    __syncthreads();

    int row0w = blockIdx.x*256 + w*32;
    const float* zwarp = z + (size_t)row0w*DZ;
    int lr8 = lane >> 3, lc8 = (lane & 7) << 2;

    wmma::fragment<wmma::accumulator,16,16,16,float> acc[2];
    wmma::fill_fragment(acc[0], 0.f);
    wmma::fill_fragment(acc[1], 0.f);
    float sumj[8], ssqj[8];
    #pragma unroll
    for (int j = 0; j < 8; j++) { sumj[j] = 0.f; ssqj[j] = 0.f; }

    bf16 (*zh)[40] = ztile[w][0];
    bf16 (*zl)[40] = ztile[w][1];

    float4 cur[8];
    #pragma unroll
    for (int j = 0; j < 8; j++)
        cur[j] = *(const float4*)&zwarp[(size_t)(j*4 + lr8)*DZ + lc8];

    for (int ch = 0; ch < 4; ch++) {
        // split + stats from registers
        #pragma unroll
        for (int j = 0; j < 8; j++) {
            float vr[4] = {cur[j].x, cur[j].y, cur[j].z, cur[j].w};
            union { bf16 h[4]; uint2 u; } H, L;
            #pragma unroll
            for (int e = 0; e < 4; e++) {
                H.h[e] = __float2bfloat16(vr[e]);
                L.h[e] = __float2bfloat16(vr[e] - __bfloat162float(H.h[e]));
                sumj[j] += vr[e];
                ssqj[j] = fmaf(vr[e], vr[e], ssqj[j]);
            }
            *(uint2*)&zh[j*4 + lr8][lc8] = H.u;
            *(uint2*)&zl[j*4 + lr8][lc8] = L.u;
        }
        __syncwarp();
        // prefetch next chunk while MMAs run
        if (ch < 3) {
            #pragma unroll
            for (int j = 0; j < 8; j++)
                cur[j] = *(const float4*)&zwarp[(size_t)(j*4 + lr8)*DZ + (ch+1)*32 + lc8];
        }
        #pragma unroll
        for (int kt = 0; kt < 2; kt++) {
            wmma::fragment<wmma::matrix_b,16,16,16,bf16,wmma::row_major> fbh, fbl;
            wmma::load_matrix_sync(fbh, &wzh[ch*32 + kt*16][0], 16);
            wmma::load_matrix_sync(fbl, &wzl[ch*32 + kt*16][0], 16);
            #pragma unroll
            for (int rt = 0; rt < 2; rt++) {
                wmma::fragment<wmma::matrix_a,16,16,16,bf16,wmma::row_major> fah, fal;
                wmma::load_matrix_sync(fah, &zh[rt*16][kt*16], 40);
                wmma::load_matrix_sync(fal, &zl[rt*16][kt*16], 40);
                wmma::mma_sync(acc[rt], fah, fbh, acc[rt]);
                wmma::mma_sync(acc[rt], fah, fbl, acc[rt]);
                wmma::mma_sync(acc[rt], fal, fbh, acc[rt]);
            }
        }
        __syncwarp();
    }

    // reduce stats across the 8 lanes of each column group (same rows)
    #pragma unroll
    for (int j = 0; j < 8; j++) {
        #pragma unroll
        for (int o = 1; o < 8; o <<= 1) {
            sumj[j] += __shfl_xor_sync(0xffffffffu, sumj[j], o);
            ssqj[j] += __shfl_xor_sync(0xffffffffu, ssqj[j], o);
        }
    }
    // route row `lane`'s stats to lane: row r=lane lives in group k=lane&3, slot j=lane>>2
    int srcLane = (lane & 3) * 8;
    float sum_own = 0.f, ssq_own = 0.f;
    #pragma unroll
    for (int j = 0; j < 8; j++) {
        float s_ = __shfl_sync(0xffffffffu, sumj[j], srcLane);
        float q_ = __shfl_sync(0xffffffffu, ssqj[j], srcLane);
        if ((lane >> 2) == j) { sum_own = s_; ssq_own = q_; }
    }

    float* Cs = (float*)ztile[w];
    wmma::store_matrix_sync(Cs,          acc[0], 20, wmma::mem_row_major);
    wmma::store_matrix_sync(Cs + 16*20,  acc[1], 20, wmma::mem_row_major);
    __syncwarp();

    float mu = sum_own * (1.f/DZ);
    float var = ssq_own * (1.f/DZ) - mu*mu;
    float rstd = rsqrtf(var + 1e-5f);
    int row = row0w + lane;
    #pragma unroll
    for (int h = 0; h < NHEAD; h++) {
        float a = Cs[lane*20 + h];
        g_scores[(size_t)h*NN + row] = rstd*(a - mu*g_alpha[h]) + g_beta[h];
    }
}

// Flash attention: one block per (q-tile 64, head). S=QK^T+zb, online softmax, O=P@V.
__global__ __launch_bounds__(256) void flash_kernel()
{
    __shared__ float Qs[32][68];
    __shared__ float Ks[32][68];
    __shared__ float Vs[64][36];
    __shared__ float Ps[64][68];
    __shared__ float corr_s[64];
    __shared__ float l_s[64];
    int tid = threadIdx.x;
    int h = blockIdx.y, q0 = blockIdx.x*64;
    const float* qb = g_q + h*NSEQ*HDIM;
    const float* kp = g_k + h*NSEQ*HDIM;
    const float* vp = g_v + h*NSEQ*HDIM;
    const float* zp = g_scores + (size_t)h*NN;

    int lr = tid >> 2;
    int lc = (tid & 3) << 2;
    {
        float4 a = *(const float4*)&qb[(q0+lr)*HDIM + lc];
        float4 b = *(const float4*)&qb[(q0+lr)*HDIM + lc + 16];
        Qs[lc+0][lr]=a.x; Qs[lc+1][lr]=a.y; Qs[lc+2][lr]=a.z; Qs[lc+3][lr]=a.w;
        Qs[lc+16][lr]=b.x; Qs[lc+17][lr]=b.y; Qs[lc+18][lr]=b.z; Qs[lc+19][lr]=b.w;
    }
    int tx = tid & 15, ty = tid >> 4;
    int oty = tid >> 3, otx = tid & 7;
    int vc = (tid & 3) << 3;
    float m[4], l[4];
    #pragma unroll
    for (int i = 0; i < 4; i++) { m[i] = -1e30f; l[i] = 0.f; }
    float oacc[2][4] = {};

    for (int kb0 = 0; kb0 < NSEQ; kb0 += 64) {
        float4 ka = *(const float4*)&kp[(kb0+lr)*HDIM + lc];
        float4 kc2 = *(const float4*)&kp[(kb0+lr)*HDIM + lc + 16];
        float4 v0 = *(const float4*)&vp[(kb0+lr)*HDIM + vc];
        float4 v1 = *(const float4*)&vp[(kb0+lr)*HDIM + vc + 4];
        __syncthreads();
        Ks[lc+0][lr]=ka.x; Ks[lc+1][lr]=ka.y; Ks[lc+2][lr]=ka.z; Ks[lc+3][lr]=ka.w;
        Ks[lc+16][lr]=kc2.x; Ks[lc+17][lr]=kc2.y; Ks[lc+18][lr]=kc2.z; Ks[lc+19][lr]=kc2.w;
        *(float4*)&Vs[lr][vc] = v0;
        *(float4*)&Vs[lr][vc+4] = v1;
        __syncthreads();

        float s[4][4];
        #pragma unroll
        for (int i = 0; i < 4; i++) {
            float4 z4 = *(const float4*)&zp[(size_t)(q0+(ty<<2)+i)*NSEQ + kb0 + (tx<<2)];
            s[i][0]=z4.x; s[i][1]=z4.y; s[i][2]=z4.z; s[i][3]=z4.w;
        }
        #pragma unroll
        for (int kk = 0; kk < 32; kk++) {
            float4 a4 = *(const float4*)&Qs[kk][ty << 2];
            float4 b4 = *(const float4*)&Ks[kk][tx << 2];
            float ar[4] = {a4.x,a4.y,a4.z,a4.w};
            float br[4] = {b4.x,b4.y,b4.z,b4.w};
            #pragma unroll
            for (int i = 0; i < 4; i++)
                #pragma unroll
                for (int j = 0; j < 4; j++)
                    s[i][j] = fmaf(ar[i], br[j], s[i][j]);
        }
        #pragma unroll
        for (int i = 0; i < 4; i++) {
            float mx = fmaxf(fmaxf(s[i][0],s[i][1]), fmaxf(s[i][2],s[i][3]));
            mx = fmaxf(mx, __shfl_xor_sync(0xffffffffu, mx, 1));
            mx = fmaxf(mx, __shfl_xor_sync(0xffffffffu, mx, 2));
            mx = fmaxf(mx, __shfl_xor_sync(0xffffffffu, mx, 4));
            mx = fmaxf(mx, __shfl_xor_sync(0xffffffffu, mx, 8));
            float mnew = fmaxf(m[i], mx);
            float c = __expf(m[i] - mnew);
            s[i][0] = __expf(s[i][0]-mnew); s[i][1] = __expf(s[i][1]-mnew);
            s[i][2] = __expf(s[i][2]-mnew); s[i][3] = __expf(s[i][3]-mnew);
            float rs = s[i][0]+s[i][1]+s[i][2]+s[i][3];
            rs += __shfl_xor_sync(0xffffffffu, rs, 1);
            rs += __shfl_xor_sync(0xffffffffu, rs, 2);
            rs += __shfl_xor_sync(0xffffffffu, rs, 4);
            rs += __shfl_xor_sync(0xffffffffu, rs, 8);
            l[i] = l[i]*c + rs;
            m[i] = mnew;
            int row = (ty << 2) + i;
            if (tx == 0) { corr_s[row] = c; l_s[row] = l[i]; }
            *(float4*)&Ps[row][tx << 2] = make_float4(s[i][0],s[i][1],s[i][2],s[i][3]);
        }
        __syncthreads();

        float c0 = corr_s[oty*2], c1 = corr_s[oty*2+1];
        #pragma unroll
        for (int j = 0; j < 4; j++) { oacc[0][j] *= c0; oacc[1][j] *= c1; }
        #pragma unroll
        for (int kk = 0; kk < 64; kk++) {
            float p0 = Ps[oty*2][kk];
            float p1 = Ps[oty*2+1][kk];
            float4 vv = *(const float4*)&Vs[kk][otx << 2];
            oacc[0][0]=fmaf(p0,vv.x,oacc[0][0]); oacc[0][1]=fmaf(p0,vv.y,oacc[0][1]);
            oacc[0][2]=fmaf(p0,vv.z,oacc[0][2]); oacc[0][3]=fmaf(p0,vv.w,oacc[0][3]);
            oacc[1][0]=fmaf(p1,vv.x,oacc[1][0]); oacc[1][1]=fmaf(p1,vv.y,oacc[1][1]);
            oacc[1][2]=fmaf(p1,vv.z,oacc[1][2]); oacc[1][3]=fmaf(p1,vv.w,oacc[1][3]);
        }
    }
    float inv0 = 1.f / l_s[oty*2];
    float inv1 = 1.f / l_s[oty*2+1];
    *(float4*)&g_o[(q0 + oty*2 + 0)*DMOD + h*HDIM + (otx << 2)] =
        make_float4(oacc[0][0]*inv0, oacc[0][1]*inv0, oacc[0][2]*inv0, oacc[0][3]*inv0);
    *(float4*)&g_o[(q0 + oty*2 + 1)*DMOD + h*HDIM + (otx << 2)] =
        make_float4(oacc[1][0]*inv1, oacc[1][1]*inv1, oacc[1][2]*inv1, oacc[1][3]*inv1);
}

extern "C" void kernel_launch(void* const* d_in, const int* in_sizes, int n_in,
                              void* d_out, int out_size)
{
    const float* s   = (const float*)d_in[0];
    const float* z   = (const float*)d_in[1];
    const float* nsw = (const float*)d_in[2];
    const float* nsb = (const float*)d_in[3];
    const float* Wq  = (const float*)d_in[4];
    const float* bq  = (const float*)d_in[5];
    const float* Wk  = (const float*)d_in[6];
    const float* Wv  = (const float*)d_in[7];
    const float* Wg  = (const float*)d_in[8];
    const float* zw  = (const float*)d_in[9];
    const float* zb  = (const float*)d_in[10];
    const float* Wz  = (const float*)d_in[11];
    const float* Wo  = (const float*)d_in[12];
    float* out = (float*)d_out;

    cudaFuncSetAttribute(tc_gemm, cudaFuncAttributeMaxDynamicSharedMemorySize, 73728);

    prep_kernel<<<1, 256>>>(Wz, zw, zb);
    ln_s_kernel<<<NSEQ, 128>>>(s, nsw, nsb);
    wtrans_kernel<<<dim3(16,16,5), dim3(32,8)>>>(Wq, Wk, Wv, Wg, Wo);
    tc_gemm<<<dim3(8,16,4), 256, 73728>>>(bq, nullptr, -1);
    zbias_kernel<<<NN/256, 256>>>(z);
    flash_kernel<<<dim3(NSEQ/64, NHEAD), 256>>>();
    conv_o_kernel<<<NSEQ*DMOD/4/256, 256>>>();
    tc_gemm<<<dim3(8,16,1), 256, 73728>>>(bq, out, 4);
}